// round 5
// baseline (speedup 1.0000x reference)
#include <cuda_runtime.h>
#include <cuda_bf16.h>

// Problem constants
#define NN   32768
#define FIN  128
#define CC   256
#define HH   4
#define FH   64
#define EE   524288
#define BB   64
#define NPG  512
#define K1   256
#define K2   128

// ---------------- scratch (device globals; no allocation allowed) ----------
__device__ float    g_hlin[NN * CC];
__device__ float    g_hout[NN * CC];
__device__ float    g_es[NN * HH];
__device__ float    g_ed[NN * HH];
__device__ float    g_dinv[NN * HH];
__device__ float    g_aself[NN * HH];
__device__ float    g_ex[EE * HH];
__device__ int      g_deg[NN];
__device__ int      g_off[NN + 1];
__device__ int      g_cur[NN];
__device__ int      g_csrc[EE];
__device__ float    g_sel[(BB * K1) * CC];
__device__ float    g_pool1[(BB * K1) * CC];
__device__ float    g_pool2[(BB * K2) * CC];
__device__ int      g_idx[BB * K1];
__device__ float    g_scores[NN];
__device__ float    g_gmean[BB * CC];
__device__ float    g_fc1[BB * 64];

__device__ __forceinline__ float leaky(float x) { return x > 0.f ? x : 0.2f * x; }

// ---------------- packed f32x2 helpers (sm_103a FFMA2) ----------------------
__device__ __forceinline__ void ffma2(unsigned long long& d, unsigned long long a,
                                      unsigned long long b) {
    asm("fma.rn.f32x2 %0, %1, %2, %0;" : "+l"(d) : "l"(a), "l"(b));
}
__device__ __forceinline__ unsigned long long pack2(float x, float y) {
    unsigned long long r;
    asm("mov.b64 %0, {%1, %2};" : "=l"(r) : "f"(x), "f"(y));
    return r;
}
__device__ __forceinline__ float2 unpack2(unsigned long long v) {
    float2 r;
    asm("mov.b64 {%0, %1}, %2;" : "=f"(r.x), "=f"(r.y) : "l"(v));
    return r;
}

// ---------------- SGEMM: C[M,N] = A[M,K] @ B[K,N] (+bias), fp32 ------------
// 128x128 tile, 256 threads, 8x8 microtile via packed FFMA2, BK=16,
// double-buffered smem. Requires M%128==0, N%128==0, K%16==0.
#define ASTRIDE 132
__global__ void __launch_bounds__(256, 2)
sgemm128(const float* __restrict__ A, const float* __restrict__ Bm,
         const float* __restrict__ bias, float* __restrict__ Cm,
         int M, int N, int K) {
    __shared__ float As[2][16][ASTRIDE];
    __shared__ float Bs[2][16][ASTRIDE];
    const int tid = threadIdx.x;
    const int row0 = blockIdx.y * 128;
    const int col0 = blockIdx.x * 128;
    const int ar = tid >> 2, ac = (tid & 3) << 2;
    const int br = tid >> 5, bc = (tid & 31) << 2;
    const int tx = tid & 15, ty = tid >> 4;
    const float* Ap = A + (size_t)(row0 + ar) * K;
    const float* Ap2 = Ap + (size_t)64 * K;

    float4 a0, a1, b0, b1;
    a0 = *(const float4*)(Ap + ac);
    a1 = *(const float4*)(Ap2 + ac);
    b0 = *(const float4*)(Bm + (size_t)br * N + col0 + bc);
    b1 = *(const float4*)(Bm + (size_t)(br + 8) * N + col0 + bc);
    As[0][ac + 0][ar] = a0.x; As[0][ac + 1][ar] = a0.y;
    As[0][ac + 2][ar] = a0.z; As[0][ac + 3][ar] = a0.w;
    As[0][ac + 0][ar + 64] = a1.x; As[0][ac + 1][ar + 64] = a1.y;
    As[0][ac + 2][ar + 64] = a1.z; As[0][ac + 3][ar + 64] = a1.w;
    *(float4*)&Bs[0][br][bc] = b0;
    *(float4*)&Bs[0][br + 8][bc] = b1;
    __syncthreads();

    unsigned long long acc2[8][4];
#pragma unroll
    for (int i = 0; i < 8; i++)
#pragma unroll
        for (int j = 0; j < 4; j++) acc2[i][j] = 0ull;

    const int ntiles = K >> 4;
    int buf = 0;
    for (int kt = 0; kt < ntiles; kt++) {
        if (kt + 1 < ntiles) {
            const int k0 = (kt + 1) << 4;
            a0 = *(const float4*)(Ap + k0 + ac);
            a1 = *(const float4*)(Ap2 + k0 + ac);
            b0 = *(const float4*)(Bm + (size_t)(k0 + br) * N + col0 + bc);
            b1 = *(const float4*)(Bm + (size_t)(k0 + br + 8) * N + col0 + bc);
        }
#pragma unroll
        for (int kk = 0; kk < 16; kk++) {
            float a[8], b[8];
            *(float4*)(a)     = *(const float4*)&As[buf][kk][ty * 8];
            *(float4*)(a + 4) = *(const float4*)&As[buf][kk][ty * 8 + 4];
            *(float4*)(b)     = *(const float4*)&Bs[buf][kk][tx * 8];
            *(float4*)(b + 4) = *(const float4*)&Bs[buf][kk][tx * 8 + 4];
            unsigned long long bp[4];
            bp[0] = pack2(b[0], b[1]); bp[1] = pack2(b[2], b[3]);
            bp[2] = pack2(b[4], b[5]); bp[3] = pack2(b[6], b[7]);
#pragma unroll
            for (int i = 0; i < 8; i++) {
                const unsigned long long ad = pack2(a[i], a[i]);
                ffma2(acc2[i][0], ad, bp[0]);
                ffma2(acc2[i][1], ad, bp[1]);
                ffma2(acc2[i][2], ad, bp[2]);
                ffma2(acc2[i][3], ad, bp[3]);
            }
        }
        if (kt + 1 < ntiles) {
            __syncthreads();
            const int nb = buf ^ 1;
            As[nb][ac + 0][ar] = a0.x; As[nb][ac + 1][ar] = a0.y;
            As[nb][ac + 2][ar] = a0.z; As[nb][ac + 3][ar] = a0.w;
            As[nb][ac + 0][ar + 64] = a1.x; As[nb][ac + 1][ar + 64] = a1.y;
            As[nb][ac + 2][ar + 64] = a1.z; As[nb][ac + 3][ar + 64] = a1.w;
            *(float4*)&Bs[nb][br][bc] = b0;
            *(float4*)&Bs[nb][br + 8][bc] = b1;
            __syncthreads();
            buf = nb;
        }
    }
    float bv[8];
    if (bias) {
        *(float4*)(bv)     = *(const float4*)&bias[col0 + tx * 8];
        *(float4*)(bv + 4) = *(const float4*)&bias[col0 + tx * 8 + 4];
    } else {
#pragma unroll
        for (int j = 0; j < 8; j++) bv[j] = 0.f;
    }
#pragma unroll
    for (int i = 0; i < 8; i++) {
        const int r = row0 + ty * 8 + i;
        const float2 c0 = unpack2(acc2[i][0]);
        const float2 c1 = unpack2(acc2[i][1]);
        const float2 c2 = unpack2(acc2[i][2]);
        const float2 c3 = unpack2(acc2[i][3]);
        float4 o0, o1;
        o0.x = c0.x + bv[0]; o0.y = c0.y + bv[1];
        o0.z = c1.x + bv[2]; o0.w = c1.y + bv[3];
        o1.x = c2.x + bv[4]; o1.y = c2.y + bv[5];
        o1.z = c3.x + bv[6]; o1.w = c3.y + bv[7];
        *(float4*)&Cm[(size_t)r * N + col0 + tx * 8] = o0;
        *(float4*)&Cm[(size_t)r * N + col0 + tx * 8 + 4] = o1;
    }
}

// ---------------- CSR build -------------------------------------------------
__global__ void zero_deg() {
    const int i = blockIdx.x * blockDim.x + threadIdx.x;
    if (i < NN) g_deg[i] = 0;
}
__global__ void hist_kernel(const int* __restrict__ ei) {
    const int e = blockIdx.x * blockDim.x + threadIdx.x;
    if (e >= EE) return;
    atomicAdd(&g_deg[ei[EE + e]], 1);
}
__global__ void scan_kernel() {
    __shared__ int sh[1024];
    const int t = threadIdx.x;
    int loc[32];
    int tot = 0;
    const int base = t * 32;
#pragma unroll
    for (int i = 0; i < 32; i++) { loc[i] = tot; tot += g_deg[base + i]; }
    sh[t] = tot;
    __syncthreads();
    for (int s = 1; s < 1024; s <<= 1) {
        const int v = (t >= s) ? sh[t - s] : 0;
        __syncthreads();
        sh[t] += v;
        __syncthreads();
    }
    const int ebase = sh[t] - tot;
#pragma unroll
    for (int i = 0; i < 32; i++) {
        g_off[base + i] = ebase + loc[i];
        g_cur[base + i] = ebase + loc[i];
    }
    if (t == 0) g_off[NN] = EE;
}
__global__ void scatter_kernel(const int* __restrict__ ei) {
    const int e = blockIdx.x * blockDim.x + threadIdx.x;
    if (e >= EE) return;
    const int d = ei[EE + e];
    const int p = atomicAdd(&g_cur[d], 1);
    g_csrc[p] = ei[e];
}

// ---------------- attention logits: es/ed per (node, head) -----------------
__global__ void esed_kernel(const float* __restrict__ hlin,
                            const float* __restrict__ a_src,
                            const float* __restrict__ a_dst,
                            float* __restrict__ es, float* __restrict__ ed) {
    const int w = (blockIdx.x * blockDim.x + threadIdx.x) >> 5;  // (n*H+h)
    const int lane = threadIdx.x & 31;
    if (w >= NN * HH) return;
    const int n = w >> 2, h = w & 3;
    const float* hp = hlin + (size_t)n * CC + h * FH;
    const float v0 = hp[lane], v1 = hp[lane + 32];
    float s = v0 * a_src[h * FH + lane] + v1 * a_src[h * FH + lane + 32];
    float d = v0 * a_dst[h * FH + lane] + v1 * a_dst[h * FH + lane + 32];
#pragma unroll
    for (int o = 16; o; o >>= 1) {
        s += __shfl_xor_sync(0xffffffffu, s, o);
        d += __shfl_xor_sync(0xffffffffu, d, o);
    }
    if (lane == 0) { es[w] = s; ed[w] = d; }
}

// ---------------- fused per-dst-node softmax (no atomics) -------------------
__global__ void att_softmax(const int* __restrict__ off, const int* __restrict__ csrc,
                            const float* __restrict__ es, const float* __restrict__ ed,
                            float* __restrict__ ex, float* __restrict__ dinv,
                            float* __restrict__ aself) {
    const int n = (blockIdx.x * blockDim.x + threadIdx.x) >> 5;
    const int lane = threadIdx.x & 31;
    if (n >= NN) return;
    const float4 edv = ((const float4*)ed)[n];
    const float4 esn = ((const float4*)es)[n];
    float4 esf;
    esf.x = leaky(esn.x + edv.x); esf.y = leaky(esn.y + edv.y);
    esf.z = leaky(esn.z + edv.z); esf.w = leaky(esn.w + edv.w);
    const int o0 = off[n], o1 = off[n + 1];
    float4 mx = esf;
    for (int i = o0 + lane; i < o1; i += 32) {
        const int s = csrc[i];
        const float4 ev = ((const float4*)es)[s];
        float4 e;
        e.x = leaky(ev.x + edv.x); e.y = leaky(ev.y + edv.y);
        e.z = leaky(ev.z + edv.z); e.w = leaky(ev.w + edv.w);
        ((float4*)ex)[i] = e;
        mx.x = fmaxf(mx.x, e.x); mx.y = fmaxf(mx.y, e.y);
        mx.z = fmaxf(mx.z, e.z); mx.w = fmaxf(mx.w, e.w);
    }
#pragma unroll
    for (int o = 16; o; o >>= 1) {
        mx.x = fmaxf(mx.x, __shfl_xor_sync(0xffffffffu, mx.x, o));
        mx.y = fmaxf(mx.y, __shfl_xor_sync(0xffffffffu, mx.y, o));
        mx.z = fmaxf(mx.z, __shfl_xor_sync(0xffffffffu, mx.z, o));
        mx.w = fmaxf(mx.w, __shfl_xor_sync(0xffffffffu, mx.w, o));
    }
    float4 xs;
    xs.x = __expf(esf.x - mx.x); xs.y = __expf(esf.y - mx.y);
    xs.z = __expf(esf.z - mx.z); xs.w = __expf(esf.w - mx.w);
    float4 sm;
    sm.x = (lane == 0) ? xs.x : 0.f; sm.y = (lane == 0) ? xs.y : 0.f;
    sm.z = (lane == 0) ? xs.z : 0.f; sm.w = (lane == 0) ? xs.w : 0.f;
    for (int i = o0 + lane; i < o1; i += 32) {
        float4 e = ((const float4*)ex)[i];
        float4 t;
        t.x = __expf(e.x - mx.x); t.y = __expf(e.y - mx.y);
        t.z = __expf(e.z - mx.z); t.w = __expf(e.w - mx.w);
        ((float4*)ex)[i] = t;
        sm.x += t.x; sm.y += t.y; sm.z += t.z; sm.w += t.w;
    }
#pragma unroll
    for (int o = 16; o; o >>= 1) {
        sm.x += __shfl_xor_sync(0xffffffffu, sm.x, o);
        sm.y += __shfl_xor_sync(0xffffffffu, sm.y, o);
        sm.z += __shfl_xor_sync(0xffffffffu, sm.z, o);
        sm.w += __shfl_xor_sync(0xffffffffu, sm.w, o);
    }
    if (lane == 0) {
        float4 iv;
        iv.x = 1.f / (sm.x + 1e-16f); iv.y = 1.f / (sm.y + 1e-16f);
        iv.z = 1.f / (sm.z + 1e-16f); iv.w = 1.f / (sm.w + 1e-16f);
        ((float4*)dinv)[n] = iv;
        float4 as;
        as.x = xs.x * iv.x; as.y = xs.y * iv.y;
        as.z = xs.z * iv.z; as.w = xs.w * iv.w;
        ((float4*)aself)[n] = as;
    }
}

// ---------------- smem-staged aggregate + bias + ELU ------------------------
// Grid: (8 col-chunks, 64 graphs). Each CTA stages its graph's 512x32 h-tile
// in shared memory (64 KB), then 8 warps each process 64 dst nodes, reading
// neighbor rows from smem (conflict-free, lane = column).
// One 32-col chunk lies entirely within one head -> scalar alpha per edge.
#define AGG_SMEM (512 * 32 * 4)
__global__ void __launch_bounds__(256)
agg_smem(const int* __restrict__ off, const int* __restrict__ csrc,
         const float* __restrict__ ex, const float* __restrict__ dinv,
         const float* __restrict__ aself, const float* __restrict__ hlin,
         const float* __restrict__ bias, float* __restrict__ out) {
    extern __shared__ float sh[];  // [512][32]
    const int chunk = blockIdx.x;            // 0..7
    const int g = blockIdx.y;                // 0..63
    const int h = chunk >> 1;
    const int cb = chunk * 32;
    const int tid = threadIdx.x, wid = tid >> 5, lane = tid & 31;
    const int nbase = g * 512;

    // stage tile: 512 rows x 32 cols (each thread: 16 float4 loads)
#pragma unroll
    for (int i = 0; i < 16; i++) {
        const int idx = tid + i * 256;       // 0..4095
        const int r = idx >> 3, q = (idx & 7) << 2;
        *(float4*)&sh[r * 32 + q] =
            *(const float4*)&hlin[(size_t)(nbase + r) * CC + cb + q];
    }
    __syncthreads();

    const float bv = bias[cb + lane];
#pragma unroll 1
    for (int j = 0; j < 64; j++) {
        const int nloc = wid * 64 + j;
        const int n = nbase + nloc;
        const int o0 = off[n], o1 = off[n + 1];
        const float dv = dinv[n * 4 + h];
        float acc = aself[n * 4 + h] * sh[nloc * 32 + lane];
        for (int i = o0; i < o1; i++) {
            const int sloc = csrc[i] - nbase;
            const float al = ex[i * 4 + h] * dv;
            acc += al * sh[sloc * 32 + lane];
        }
        const float v = acc + bv;
        out[(size_t)n * CC + cb + lane] = v > 0.f ? v : (__expf(v) - 1.f);
    }
}

// ---------------- pooling ---------------------------------------------------
__global__ void score_kernel(const float* __restrict__ X, const float* __restrict__ sw,
                             const float* __restrict__ sb, float* __restrict__ scores,
                             int rows) {
    const int w = (blockIdx.x * blockDim.x + threadIdx.x) >> 5;
    const int lane = threadIdx.x & 31;
    if (w >= rows) return;
    float s = 0.f;
#pragma unroll
    for (int c = lane; c < CC; c += 32) s += X[(size_t)w * CC + c] * sw[c];
#pragma unroll
    for (int o = 16; o; o >>= 1) s += __shfl_xor_sync(0xffffffffu, s, o);
    if (lane == 0) scores[w] = 1.f / (1.f + __expf(-(s + sb[0])));
}

template <int NPB, int KSEL>
__global__ void topk_kernel(const float* __restrict__ scores, int* __restrict__ idx_out) {
    __shared__ float sv[NPB];
    __shared__ int si[NPB];
    const int b = blockIdx.x, t = threadIdx.x;
    sv[t] = scores[b * NPB + t];
    si[t] = t;
    __syncthreads();
    for (int k = 2; k <= NPB; k <<= 1) {
        for (int j = k >> 1; j > 0; j >>= 1) {
            const int ixj = t ^ j;
            if (ixj > t) {
                const bool desc = ((t & k) == 0);
                const float a = sv[t], c = sv[ixj];
                if ((a < c) == desc) {
                    sv[t] = c; sv[ixj] = a;
                    const int tmp = si[t]; si[t] = si[ixj]; si[ixj] = tmp;
                }
            }
            __syncthreads();
        }
    }
    if (t < KSEL) idx_out[b * KSEL + t] = b * NPB + si[t];
}

__global__ void gather_kernel(const float* __restrict__ X, const int* __restrict__ idx,
                              float* __restrict__ out, int rows) {
    const int g = blockIdx.x * blockDim.x + threadIdx.x;
    if (g >= rows * 64) return;
    const int r = g >> 6, c4 = (g & 63) * 4;
    const float4 v = *reinterpret_cast<const float4*>(&X[(size_t)idx[r] * CC + c4]);
    *reinterpret_cast<float4*>(&out[(size_t)r * CC + c4]) = v;
}

// ---------------- readout ---------------------------------------------------
__global__ void mean_kernel(const float* __restrict__ X, float* __restrict__ g) {
    const int i = blockIdx.x * blockDim.x + threadIdx.x;
    if (i >= BB * CC) return;
    const int b = i >> 8, c = i & 255;
    float s = 0.f;
    for (int r = 0; r < K2; r++) s += X[(size_t)(b * K2 + r) * CC + c];
    g[i] = s * (1.f / K2);
}

__global__ void fc1_kernel(const float* __restrict__ g, const float* __restrict__ w,
                           const float* __restrict__ bias, float* __restrict__ out) {
    const int i = blockIdx.x * blockDim.x + threadIdx.x;
    if (i >= BB * 64) return;
    const int b = i >> 6, o = i & 63;
    float s = bias[o];
    for (int k = 0; k < CC; k++) s += g[b * CC + k] * w[k * 64 + o];
    out[i] = s > 0.f ? s : 0.f;
}

__global__ void fc2_lsm_kernel(const float* __restrict__ f, const float* __restrict__ w,
                               const float* __restrict__ bias, float* __restrict__ out) {
    const int b = threadIdx.x;
    if (b >= BB) return;
    float l0 = bias[0], l1 = bias[1];
    for (int k = 0; k < 64; k++) {
        const float v = f[b * 64 + k];
        l0 += v * w[k * 2 + 0];
        l1 += v * w[k * 2 + 1];
    }
    const float mm = fmaxf(l0, l1);
    const float lse = mm + logf(__expf(l0 - mm) + __expf(l1 - mm));
    out[b * 2 + 0] = l0 - lse;
    out[b * 2 + 1] = l1 - lse;
}

// ---------------- host orchestration ----------------------------------------
static float* sym(const void* s) {
    void* p = nullptr;
    cudaGetSymbolAddress(&p, (const void*)s);
    return (float*)p;
}

extern "C" void kernel_launch(void* const* d_in, const int* in_sizes, int n_in,
                              void* d_out, int out_size) {
    const float* x      = (const float*)d_in[0];
    const int*   ei     = (const int*)  d_in[1];
    const float* W1     = (const float*)d_in[3];
    const float* asrc1  = (const float*)d_in[4];
    const float* adst1  = (const float*)d_in[5];
    const float* b1     = (const float*)d_in[6];
    const float* W2     = (const float*)d_in[7];
    const float* asrc2  = (const float*)d_in[8];
    const float* adst2  = (const float*)d_in[9];
    const float* b2     = (const float*)d_in[10];
    const float* p1_sw  = (const float*)d_in[11];
    const float* p1_sb  = (const float*)d_in[12];
    const float* p1_tw  = (const float*)d_in[13];
    const float* p1_tb  = (const float*)d_in[14];
    const float* p2_sw  = (const float*)d_in[15];
    const float* p2_sb  = (const float*)d_in[16];
    const float* p2_tw  = (const float*)d_in[17];
    const float* p2_tb  = (const float*)d_in[18];
    const float* c1w    = (const float*)d_in[19];
    const float* c1b    = (const float*)d_in[20];
    const float* c2w    = (const float*)d_in[21];
    const float* c2b    = (const float*)d_in[22];
    float* out = (float*)d_out;

    float*    hlin  = sym(g_hlin);
    float*    hout  = sym(g_hout);
    float*    es    = sym(g_es);
    float*    ed    = sym(g_ed);
    float*    dinv  = sym(g_dinv);
    float*    aself = sym(g_aself);
    float*    ex    = sym(g_ex);
    int*      off   = (int*)sym(g_off);
    int*      csrc  = (int*)sym(g_csrc);
    float*    selb  = sym(g_sel);
    float*    pool1 = sym(g_pool1);
    float*    pool2 = sym(g_pool2);
    int*      idx   = (int*)sym(g_idx);
    float*    sc    = sym(g_scores);
    float*    gmean = sym(g_gmean);
    float*    fc1   = sym(g_fc1);

    cudaFuncSetAttribute(agg_smem, cudaFuncAttributeMaxDynamicSharedMemorySize, AGG_SMEM);

    dim3 t256(256);
    dim3 agg_grid(8, BB);

    // ---- CSR build (graph shared by both layers) ----
    zero_deg<<<NN / 256, t256>>>();
    hist_kernel<<<EE / 256, t256>>>(ei);
    scan_kernel<<<1, 1024>>>();
    scatter_kernel<<<EE / 256, t256>>>(ei);

    // ---- GAT layer 1 ----
    sgemm128<<<dim3(CC / 128, NN / 128), t256>>>(x, W1, nullptr, hlin, NN, CC, FIN);
    esed_kernel<<<(NN * HH) / 8, t256>>>(hlin, asrc1, adst1, es, ed);
    att_softmax<<<(NN * 32) / 256, t256>>>(off, csrc, es, ed, ex, dinv, aself);
    agg_smem<<<agg_grid, t256, AGG_SMEM>>>(off, csrc, ex, dinv, aself, hlin, b1, hout);

    // ---- GAT layer 2 ----
    sgemm128<<<dim3(CC / 128, NN / 128), t256>>>(hout, W2, nullptr, hlin, NN, CC, CC);
    esed_kernel<<<(NN * HH) / 8, t256>>>(hlin, asrc2, adst2, es, ed);
    att_softmax<<<(NN * 32) / 256, t256>>>(off, csrc, es, ed, ex, dinv, aself);
    agg_smem<<<agg_grid, t256, AGG_SMEM>>>(off, csrc, ex, dinv, aself, hlin, b2, hout);

    // ---- Pool 1 (top-256 of 512 per graph) ----
    score_kernel<<<(NN * 32) / 256, t256>>>(hout, p1_sw, p1_sb, sc, NN);
    topk_kernel<NPG, K1><<<BB, NPG>>>(sc, idx);
    gather_kernel<<<(BB * K1 * 64) / 256, t256>>>(hout, idx, selb, BB * K1);
    sgemm128<<<dim3(CC / 128, (BB * K1) / 128), t256>>>(selb, p1_tw, p1_tb, pool1, BB * K1, CC, CC);

    // ---- Pool 2 (top-128 of 256 per graph) ----
    score_kernel<<<(BB * K1 * 32) / 256, t256>>>(pool1, p2_sw, p2_sb, sc, BB * K1);
    topk_kernel<K1, K2><<<BB, K1>>>(sc, idx);
    gather_kernel<<<(BB * K2 * 64) / 256, t256>>>(pool1, idx, selb, BB * K2);
    sgemm128<<<dim3(CC / 128, (BB * K2) / 128), t256>>>(selb, p2_tw, p2_tb, pool2, BB * K2, CC, CC);

    // ---- readout ----
    mean_kernel<<<(BB * CC) / 256, t256>>>(pool2, gmean);
    fc1_kernel<<<(BB * 64) / 256, t256>>>(gmean, c1w, c1b, fc1);
    fc2_lsm_kernel<<<1, 64>>>(fc1, c2w, c2b, out);
}

// round 6
// speedup vs baseline: 1.4928x; 1.4928x over previous
#include <cuda_runtime.h>
#include <cuda_bf16.h>

// Problem constants
#define NN   32768
#define FIN  128
#define CC   256
#define HH   4
#define FH   64
#define EE   524288
#define BB   64
#define NPG  512
#define K1   256
#define K2   128

// ---------------- scratch (device globals; no allocation allowed) ----------
__device__ float    g_hlin[NN * CC];
__device__ float    g_hout[NN * CC];
__device__ float    g_es[NN * HH];
__device__ float    g_ed[NN * HH];
__device__ float    g_dinv[NN * HH];
__device__ float    g_aself[NN * HH];
__device__ float    g_ex[EE * HH];
__device__ int      g_deg[NN];
__device__ int      g_off[NN + 1];
__device__ int      g_cur[NN];
__device__ int      g_csrc[EE];
__device__ float    g_sel[(BB * K1) * CC];
__device__ float    g_pool1[(BB * K1) * CC];
__device__ float    g_pool2[(BB * K2) * CC];
__device__ int      g_idx[BB * K1];
__device__ float    g_scores[NN];
__device__ float    g_gmean[BB * CC];
__device__ float    g_fc1[BB * 64];

__device__ __forceinline__ float leaky(float x) { return x > 0.f ? x : 0.2f * x; }

// ---------------- packed f32x2 helpers (sm_103a FFMA2) ----------------------
__device__ __forceinline__ void ffma2(unsigned long long& d, unsigned long long a,
                                      unsigned long long b) {
    asm("fma.rn.f32x2 %0, %1, %2, %0;" : "+l"(d) : "l"(a), "l"(b));
}
__device__ __forceinline__ unsigned long long pack2(float x, float y) {
    unsigned long long r;
    asm("mov.b64 %0, {%1, %2};" : "=l"(r) : "f"(x), "f"(y));
    return r;
}
__device__ __forceinline__ float2 unpack2(unsigned long long v) {
    float2 r;
    asm("mov.b64 {%0, %1}, %2;" : "=f"(r.x), "=f"(r.y) : "l"(v));
    return r;
}

// ---------------- SGEMM: C[M,N] = A[M,K] @ B[K,N] (+bias), fp32 ------------
// 128x128 tile, 256 threads, 8x8 microtile via packed FFMA2, BK=16,
// double-buffered smem. Requires M%128==0, N%128==0, K%16==0.
#define ASTRIDE 132
__global__ void __launch_bounds__(256, 2)
sgemm128(const float* __restrict__ A, const float* __restrict__ Bm,
         const float* __restrict__ bias, float* __restrict__ Cm,
         int M, int N, int K) {
    __shared__ float As[2][16][ASTRIDE];
    __shared__ float Bs[2][16][ASTRIDE];
    const int tid = threadIdx.x;
    const int row0 = blockIdx.y * 128;
    const int col0 = blockIdx.x * 128;
    const int ar = tid >> 2, ac = (tid & 3) << 2;
    const int br = tid >> 5, bc = (tid & 31) << 2;
    const int tx = tid & 15, ty = tid >> 4;
    const float* Ap = A + (size_t)(row0 + ar) * K;
    const float* Ap2 = Ap + (size_t)64 * K;

    float4 a0, a1, b0, b1;
    a0 = *(const float4*)(Ap + ac);
    a1 = *(const float4*)(Ap2 + ac);
    b0 = *(const float4*)(Bm + (size_t)br * N + col0 + bc);
    b1 = *(const float4*)(Bm + (size_t)(br + 8) * N + col0 + bc);
    As[0][ac + 0][ar] = a0.x; As[0][ac + 1][ar] = a0.y;
    As[0][ac + 2][ar] = a0.z; As[0][ac + 3][ar] = a0.w;
    As[0][ac + 0][ar + 64] = a1.x; As[0][ac + 1][ar + 64] = a1.y;
    As[0][ac + 2][ar + 64] = a1.z; As[0][ac + 3][ar + 64] = a1.w;
    *(float4*)&Bs[0][br][bc] = b0;
    *(float4*)&Bs[0][br + 8][bc] = b1;
    __syncthreads();

    unsigned long long acc2[8][4];
#pragma unroll
    for (int i = 0; i < 8; i++)
#pragma unroll
        for (int j = 0; j < 4; j++) acc2[i][j] = 0ull;

    const int ntiles = K >> 4;
    int buf = 0;
    for (int kt = 0; kt < ntiles; kt++) {
        if (kt + 1 < ntiles) {
            const int k0 = (kt + 1) << 4;
            a0 = *(const float4*)(Ap + k0 + ac);
            a1 = *(const float4*)(Ap2 + k0 + ac);
            b0 = *(const float4*)(Bm + (size_t)(k0 + br) * N + col0 + bc);
            b1 = *(const float4*)(Bm + (size_t)(k0 + br + 8) * N + col0 + bc);
        }
#pragma unroll
        for (int kk = 0; kk < 16; kk++) {
            float a[8], b[8];
            *(float4*)(a)     = *(const float4*)&As[buf][kk][ty * 8];
            *(float4*)(a + 4) = *(const float4*)&As[buf][kk][ty * 8 + 4];
            *(float4*)(b)     = *(const float4*)&Bs[buf][kk][tx * 8];
            *(float4*)(b + 4) = *(const float4*)&Bs[buf][kk][tx * 8 + 4];
            unsigned long long bp[4];
            bp[0] = pack2(b[0], b[1]); bp[1] = pack2(b[2], b[3]);
            bp[2] = pack2(b[4], b[5]); bp[3] = pack2(b[6], b[7]);
#pragma unroll
            for (int i = 0; i < 8; i++) {
                const unsigned long long ad = pack2(a[i], a[i]);
                ffma2(acc2[i][0], ad, bp[0]);
                ffma2(acc2[i][1], ad, bp[1]);
                ffma2(acc2[i][2], ad, bp[2]);
                ffma2(acc2[i][3], ad, bp[3]);
            }
        }
        if (kt + 1 < ntiles) {
            __syncthreads();
            const int nb = buf ^ 1;
            As[nb][ac + 0][ar] = a0.x; As[nb][ac + 1][ar] = a0.y;
            As[nb][ac + 2][ar] = a0.z; As[nb][ac + 3][ar] = a0.w;
            As[nb][ac + 0][ar + 64] = a1.x; As[nb][ac + 1][ar + 64] = a1.y;
            As[nb][ac + 2][ar + 64] = a1.z; As[nb][ac + 3][ar + 64] = a1.w;
            *(float4*)&Bs[nb][br][bc] = b0;
            *(float4*)&Bs[nb][br + 8][bc] = b1;
            __syncthreads();
            buf = nb;
        }
    }
    float bv[8];
    if (bias) {
        *(float4*)(bv)     = *(const float4*)&bias[col0 + tx * 8];
        *(float4*)(bv + 4) = *(const float4*)&bias[col0 + tx * 8 + 4];
    } else {
#pragma unroll
        for (int j = 0; j < 8; j++) bv[j] = 0.f;
    }
#pragma unroll
    for (int i = 0; i < 8; i++) {
        const int r = row0 + ty * 8 + i;
        const float2 c0 = unpack2(acc2[i][0]);
        const float2 c1 = unpack2(acc2[i][1]);
        const float2 c2 = unpack2(acc2[i][2]);
        const float2 c3 = unpack2(acc2[i][3]);
        float4 o0, o1;
        o0.x = c0.x + bv[0]; o0.y = c0.y + bv[1];
        o0.z = c1.x + bv[2]; o0.w = c1.y + bv[3];
        o1.x = c2.x + bv[4]; o1.y = c2.y + bv[5];
        o1.z = c3.x + bv[6]; o1.w = c3.y + bv[7];
        *(float4*)&Cm[(size_t)r * N + col0 + tx * 8] = o0;
        *(float4*)&Cm[(size_t)r * N + col0 + tx * 8 + 4] = o1;
    }
}

// ---------------- CSR build -------------------------------------------------
__global__ void zero_deg() {
    const int i = blockIdx.x * blockDim.x + threadIdx.x;
    if (i < NN) g_deg[i] = 0;
}
__global__ void hist_kernel(const int* __restrict__ ei) {
    const int e = blockIdx.x * blockDim.x + threadIdx.x;
    if (e >= EE) return;
    atomicAdd(&g_deg[ei[EE + e]], 1);
}
__global__ void scan_kernel() {
    __shared__ int sh[1024];
    const int t = threadIdx.x;
    int loc[32];
    int tot = 0;
    const int base = t * 32;
#pragma unroll
    for (int i = 0; i < 32; i++) { loc[i] = tot; tot += g_deg[base + i]; }
    sh[t] = tot;
    __syncthreads();
    for (int s = 1; s < 1024; s <<= 1) {
        const int v = (t >= s) ? sh[t - s] : 0;
        __syncthreads();
        sh[t] += v;
        __syncthreads();
    }
    const int ebase = sh[t] - tot;
#pragma unroll
    for (int i = 0; i < 32; i++) {
        g_off[base + i] = ebase + loc[i];
        g_cur[base + i] = ebase + loc[i];
    }
    if (t == 0) g_off[NN] = EE;
}
__global__ void scatter_kernel(const int* __restrict__ ei) {
    const int e = blockIdx.x * blockDim.x + threadIdx.x;
    if (e >= EE) return;
    const int d = ei[EE + e];
    const int p = atomicAdd(&g_cur[d], 1);
    g_csrc[p] = ei[e];
}

// ---------------- attention logits: es/ed per (node, head) -----------------
__global__ void esed_kernel(const float* __restrict__ hlin,
                            const float* __restrict__ a_src,
                            const float* __restrict__ a_dst,
                            float* __restrict__ es, float* __restrict__ ed) {
    const int w = (blockIdx.x * blockDim.x + threadIdx.x) >> 5;  // (n*H+h)
    const int lane = threadIdx.x & 31;
    if (w >= NN * HH) return;
    const int n = w >> 2, h = w & 3;
    const float* hp = hlin + (size_t)n * CC + h * FH;
    const float v0 = hp[lane], v1 = hp[lane + 32];
    float s = v0 * a_src[h * FH + lane] + v1 * a_src[h * FH + lane + 32];
    float d = v0 * a_dst[h * FH + lane] + v1 * a_dst[h * FH + lane + 32];
#pragma unroll
    for (int o = 16; o; o >>= 1) {
        s += __shfl_xor_sync(0xffffffffu, s, o);
        d += __shfl_xor_sync(0xffffffffu, d, o);
    }
    if (lane == 0) { es[w] = s; ed[w] = d; }
}

// ---------------- fused per-dst-node softmax (no atomics) -------------------
__global__ void att_softmax(const int* __restrict__ off, const int* __restrict__ csrc,
                            const float* __restrict__ es, const float* __restrict__ ed,
                            float* __restrict__ ex, float* __restrict__ dinv,
                            float* __restrict__ aself) {
    const int n = (blockIdx.x * blockDim.x + threadIdx.x) >> 5;
    const int lane = threadIdx.x & 31;
    if (n >= NN) return;
    const float4 edv = ((const float4*)ed)[n];
    const float4 esn = ((const float4*)es)[n];
    float4 esf;
    esf.x = leaky(esn.x + edv.x); esf.y = leaky(esn.y + edv.y);
    esf.z = leaky(esn.z + edv.z); esf.w = leaky(esn.w + edv.w);
    const int o0 = off[n], o1 = off[n + 1];
    float4 mx = esf;
    for (int i = o0 + lane; i < o1; i += 32) {
        const int s = csrc[i];
        const float4 ev = ((const float4*)es)[s];
        float4 e;
        e.x = leaky(ev.x + edv.x); e.y = leaky(ev.y + edv.y);
        e.z = leaky(ev.z + edv.z); e.w = leaky(ev.w + edv.w);
        ((float4*)ex)[i] = e;
        mx.x = fmaxf(mx.x, e.x); mx.y = fmaxf(mx.y, e.y);
        mx.z = fmaxf(mx.z, e.z); mx.w = fmaxf(mx.w, e.w);
    }
#pragma unroll
    for (int o = 16; o; o >>= 1) {
        mx.x = fmaxf(mx.x, __shfl_xor_sync(0xffffffffu, mx.x, o));
        mx.y = fmaxf(mx.y, __shfl_xor_sync(0xffffffffu, mx.y, o));
        mx.z = fmaxf(mx.z, __shfl_xor_sync(0xffffffffu, mx.z, o));
        mx.w = fmaxf(mx.w, __shfl_xor_sync(0xffffffffu, mx.w, o));
    }
    float4 xs;
    xs.x = __expf(esf.x - mx.x); xs.y = __expf(esf.y - mx.y);
    xs.z = __expf(esf.z - mx.z); xs.w = __expf(esf.w - mx.w);
    float4 sm;
    sm.x = (lane == 0) ? xs.x : 0.f; sm.y = (lane == 0) ? xs.y : 0.f;
    sm.z = (lane == 0) ? xs.z : 0.f; sm.w = (lane == 0) ? xs.w : 0.f;
    for (int i = o0 + lane; i < o1; i += 32) {
        float4 e = ((const float4*)ex)[i];
        float4 t;
        t.x = __expf(e.x - mx.x); t.y = __expf(e.y - mx.y);
        t.z = __expf(e.z - mx.z); t.w = __expf(e.w - mx.w);
        ((float4*)ex)[i] = t;
        sm.x += t.x; sm.y += t.y; sm.z += t.z; sm.w += t.w;
    }
#pragma unroll
    for (int o = 16; o; o >>= 1) {
        sm.x += __shfl_xor_sync(0xffffffffu, sm.x, o);
        sm.y += __shfl_xor_sync(0xffffffffu, sm.y, o);
        sm.z += __shfl_xor_sync(0xffffffffu, sm.z, o);
        sm.w += __shfl_xor_sync(0xffffffffu, sm.w, o);
    }
    if (lane == 0) {
        float4 iv;
        iv.x = 1.f / (sm.x + 1e-16f); iv.y = 1.f / (sm.y + 1e-16f);
        iv.z = 1.f / (sm.z + 1e-16f); iv.w = 1.f / (sm.w + 1e-16f);
        ((float4*)dinv)[n] = iv;
        float4 as;
        as.x = xs.x * iv.x; as.y = xs.y * iv.y;
        as.z = xs.z * iv.z; as.w = xs.w * iv.w;
        ((float4*)aself)[n] = as;
    }
}

// ---------------- aggregate + bias + ELU: 2 warps per node ------------------
// Warp (n, half): covers cols half*128 .. half*128+127 (heads 2*half, 2*half+1).
// acc = alpha_self*h[n] + sum alpha_e*h[s]; out = elu(acc + bias).
__global__ void agg_csr2(const int* __restrict__ off, const int* __restrict__ csrc,
                         const float* __restrict__ ex, const float* __restrict__ dinv,
                         const float* __restrict__ aself, const float* __restrict__ hlin,
                         const float* __restrict__ bias, float* __restrict__ out) {
    const int w = (blockIdx.x * blockDim.x + threadIdx.x) >> 5;
    const int lane = threadIdx.x & 31;
    if (w >= 2 * NN) return;
    const int n = w >> 1, half = w & 1;
    const int cbase = half * 128;
    const float2 dv = ((const float2*)dinv)[n * 2 + half];
    const float2 av = ((const float2*)aself)[n * 2 + half];
    const float di[2] = {dv.x, dv.y};
    const float asf[2] = {av.x, av.y};
    float acc[4];
    const float* hn = hlin + (size_t)n * CC + cbase;
#pragma unroll
    for (int j = 0; j < 4; j++) acc[j] = asf[j >> 1] * hn[lane + 32 * j];
    const int o0 = off[n], o1 = off[n + 1];
    int s_next = 0;
    float2 e_next = {0.f, 0.f};
    if (o0 < o1) {
        s_next = csrc[o0];
        e_next = ((const float2*)ex)[o0 * 2 + half];
    }
    for (int i = o0; i < o1; i++) {
        const int s = s_next;
        const float2 e2 = e_next;
        if (i + 1 < o1) {
            s_next = csrc[i + 1];
            e_next = ((const float2*)ex)[(i + 1) * 2 + half];
        }
        const float al[2] = {e2.x * di[0], e2.y * di[1]};
        const float* hs = hlin + (size_t)s * CC + cbase;
#pragma unroll
        for (int j = 0; j < 4; j++) acc[j] += al[j >> 1] * hs[lane + 32 * j];
    }
#pragma unroll
    for (int j = 0; j < 4; j++) {
        const int c = cbase + lane + 32 * j;
        const float v = acc[j] + bias[c];
        out[(size_t)n * CC + c] = v > 0.f ? v : (__expf(v) - 1.f);
    }
}

// ---------------- pooling ---------------------------------------------------
__global__ void score_kernel(const float* __restrict__ X, const float* __restrict__ sw,
                             const float* __restrict__ sb, float* __restrict__ scores,
                             int rows) {
    const int w = (blockIdx.x * blockDim.x + threadIdx.x) >> 5;
    const int lane = threadIdx.x & 31;
    if (w >= rows) return;
    float s = 0.f;
#pragma unroll
    for (int c = lane; c < CC; c += 32) s += X[(size_t)w * CC + c] * sw[c];
#pragma unroll
    for (int o = 16; o; o >>= 1) s += __shfl_xor_sync(0xffffffffu, s, o);
    if (lane == 0) scores[w] = 1.f / (1.f + __expf(-(s + sb[0])));
}

template <int NPB, int KSEL>
__global__ void topk_kernel(const float* __restrict__ scores, int* __restrict__ idx_out) {
    __shared__ float sv[NPB];
    __shared__ int si[NPB];
    const int b = blockIdx.x, t = threadIdx.x;
    sv[t] = scores[b * NPB + t];
    si[t] = t;
    __syncthreads();
    for (int k = 2; k <= NPB; k <<= 1) {
        for (int j = k >> 1; j > 0; j >>= 1) {
            const int ixj = t ^ j;
            if (ixj > t) {
                const bool desc = ((t & k) == 0);
                const float a = sv[t], c = sv[ixj];
                if ((a < c) == desc) {
                    sv[t] = c; sv[ixj] = a;
                    const int tmp = si[t]; si[t] = si[ixj]; si[ixj] = tmp;
                }
            }
            __syncthreads();
        }
    }
    if (t < KSEL) idx_out[b * KSEL + t] = b * NPB + si[t];
}

__global__ void gather_kernel(const float* __restrict__ X, const int* __restrict__ idx,
                              float* __restrict__ out, int rows) {
    const int g = blockIdx.x * blockDim.x + threadIdx.x;
    if (g >= rows * 64) return;
    const int r = g >> 6, c4 = (g & 63) * 4;
    const float4 v = *reinterpret_cast<const float4*>(&X[(size_t)idx[r] * CC + c4]);
    *reinterpret_cast<float4*>(&out[(size_t)r * CC + c4]) = v;
}

// ---------------- readout ---------------------------------------------------
__global__ void mean_kernel(const float* __restrict__ X, float* __restrict__ g) {
    const int i = blockIdx.x * blockDim.x + threadIdx.x;
    if (i >= BB * CC) return;
    const int b = i >> 8, c = i & 255;
    float s = 0.f;
    for (int r = 0; r < K2; r++) s += X[(size_t)(b * K2 + r) * CC + c];
    g[i] = s * (1.f / K2);
}

__global__ void fc1_kernel(const float* __restrict__ g, const float* __restrict__ w,
                           const float* __restrict__ bias, float* __restrict__ out) {
    const int i = blockIdx.x * blockDim.x + threadIdx.x;
    if (i >= BB * 64) return;
    const int b = i >> 6, o = i & 63;
    float s = bias[o];
    for (int k = 0; k < CC; k++) s += g[b * CC + k] * w[k * 64 + o];
    out[i] = s > 0.f ? s : 0.f;
}

__global__ void fc2_lsm_kernel(const float* __restrict__ f, const float* __restrict__ w,
                               const float* __restrict__ bias, float* __restrict__ out) {
    const int b = threadIdx.x;
    if (b >= BB) return;
    float l0 = bias[0], l1 = bias[1];
    for (int k = 0; k < 64; k++) {
        const float v = f[b * 64 + k];
        l0 += v * w[k * 2 + 0];
        l1 += v * w[k * 2 + 1];
    }
    const float mm = fmaxf(l0, l1);
    const float lse = mm + logf(__expf(l0 - mm) + __expf(l1 - mm));
    out[b * 2 + 0] = l0 - lse;
    out[b * 2 + 1] = l1 - lse;
}

// ---------------- host orchestration ----------------------------------------
static float* sym(const void* s) {
    void* p = nullptr;
    cudaGetSymbolAddress(&p, (const void*)s);
    return (float*)p;
}

extern "C" void kernel_launch(void* const* d_in, const int* in_sizes, int n_in,
                              void* d_out, int out_size) {
    const float* x      = (const float*)d_in[0];
    const int*   ei     = (const int*)  d_in[1];
    const float* W1     = (const float*)d_in[3];
    const float* asrc1  = (const float*)d_in[4];
    const float* adst1  = (const float*)d_in[5];
    const float* b1     = (const float*)d_in[6];
    const float* W2     = (const float*)d_in[7];
    const float* asrc2  = (const float*)d_in[8];
    const float* adst2  = (const float*)d_in[9];
    const float* b2     = (const float*)d_in[10];
    const float* p1_sw  = (const float*)d_in[11];
    const float* p1_sb  = (const float*)d_in[12];
    const float* p1_tw  = (const float*)d_in[13];
    const float* p1_tb  = (const float*)d_in[14];
    const float* p2_sw  = (const float*)d_in[15];
    const float* p2_sb  = (const float*)d_in[16];
    const float* p2_tw  = (const float*)d_in[17];
    const float* p2_tb  = (const float*)d_in[18];
    const float* c1w    = (const float*)d_in[19];
    const float* c1b    = (const float*)d_in[20];
    const float* c2w    = (const float*)d_in[21];
    const float* c2b    = (const float*)d_in[22];
    float* out = (float*)d_out;

    float*    hlin  = sym(g_hlin);
    float*    hout  = sym(g_hout);
    float*    es    = sym(g_es);
    float*    ed    = sym(g_ed);
    float*    dinv  = sym(g_dinv);
    float*    aself = sym(g_aself);
    float*    ex    = sym(g_ex);
    int*      off   = (int*)sym(g_off);
    int*      csrc  = (int*)sym(g_csrc);
    float*    selb  = sym(g_sel);
    float*    pool1 = sym(g_pool1);
    float*    pool2 = sym(g_pool2);
    int*      idx   = (int*)sym(g_idx);
    float*    sc    = sym(g_scores);
    float*    gmean = sym(g_gmean);
    float*    fc1   = sym(g_fc1);

    dim3 t256(256);

    // ---- CSR build (graph shared by both layers) ----
    zero_deg<<<NN / 256, t256>>>();
    hist_kernel<<<EE / 256, t256>>>(ei);
    scan_kernel<<<1, 1024>>>();
    scatter_kernel<<<EE / 256, t256>>>(ei);

    // ---- GAT layer 1 ----
    sgemm128<<<dim3(CC / 128, NN / 128), t256>>>(x, W1, nullptr, hlin, NN, CC, FIN);
    esed_kernel<<<(NN * HH) / 8, t256>>>(hlin, asrc1, adst1, es, ed);
    att_softmax<<<(NN * 32) / 256, t256>>>(off, csrc, es, ed, ex, dinv, aself);
    agg_csr2<<<(2 * NN * 32) / 256, t256>>>(off, csrc, ex, dinv, aself, hlin, b1, hout);

    // ---- GAT layer 2 ----
    sgemm128<<<dim3(CC / 128, NN / 128), t256>>>(hout, W2, nullptr, hlin, NN, CC, CC);
    esed_kernel<<<(NN * HH) / 8, t256>>>(hlin, asrc2, adst2, es, ed);
    att_softmax<<<(NN * 32) / 256, t256>>>(off, csrc, es, ed, ex, dinv, aself);
    agg_csr2<<<(2 * NN * 32) / 256, t256>>>(off, csrc, ex, dinv, aself, hlin, b2, hout);

    // ---- Pool 1 (top-256 of 512 per graph) ----
    score_kernel<<<(NN * 32) / 256, t256>>>(hout, p1_sw, p1_sb, sc, NN);
    topk_kernel<NPG, K1><<<BB, NPG>>>(sc, idx);
    gather_kernel<<<(BB * K1 * 64) / 256, t256>>>(hout, idx, selb, BB * K1);
    sgemm128<<<dim3(CC / 128, (BB * K1) / 128), t256>>>(selb, p1_tw, p1_tb, pool1, BB * K1, CC, CC);

    // ---- Pool 2 (top-128 of 256 per graph) ----
    score_kernel<<<(BB * K1 * 32) / 256, t256>>>(pool1, p2_sw, p2_sb, sc, BB * K1);
    topk_kernel<K1, K2><<<BB, K1>>>(sc, idx);
    gather_kernel<<<(BB * K2 * 64) / 256, t256>>>(pool1, idx, selb, BB * K2);
    sgemm128<<<dim3(CC / 128, (BB * K2) / 128), t256>>>(selb, p2_tw, p2_tb, pool2, BB * K2, CC, CC);

    // ---- readout ----
    mean_kernel<<<(BB * CC) / 256, t256>>>(pool2, gmean);
    fc1_kernel<<<(BB * 64) / 256, t256>>>(gmean, c1w, c1b, fc1);
    fc2_lsm_kernel<<<1, 64>>>(fc1, c2w, c2b, out);
}

// round 7
// speedup vs baseline: 1.7999x; 1.2057x over previous
#include <cuda_runtime.h>
#include <cuda_bf16.h>

// Problem constants
#define NN   32768
#define FIN  128
#define CC   256
#define HH   4
#define FH   64
#define EE   524288
#define BB   64
#define NPG  512
#define EPG  (EE / BB)   // 8192 edges per graph, contiguous in edge list
#define K1   256
#define K2   128

// ---------------- scratch (device globals; no allocation allowed) ----------
__device__ float    g_hlin[NN * CC];
__device__ float    g_hout[NN * CC];
__device__ float    g_es[NN * HH];
__device__ float    g_ed[NN * HH];
__device__ int      g_off[NN + 1];
__device__ int      g_csrc[EE];
__device__ float    g_sel[(BB * K1) * CC];
__device__ float    g_pool1[(BB * K1) * CC];
__device__ float    g_pool2[(BB * K2) * CC];
__device__ int      g_idx[BB * K1];
__device__ float    g_scores[NN];
__device__ float    g_gmean[BB * CC];
__device__ float    g_fc1[BB * 64];

__device__ __forceinline__ float leaky(float x) { return x > 0.f ? x : 0.2f * x; }

// ---------------- packed f32x2 helpers (sm_103a FFMA2) ----------------------
__device__ __forceinline__ void ffma2(unsigned long long& d, unsigned long long a,
                                      unsigned long long b) {
    asm("fma.rn.f32x2 %0, %1, %2, %0;" : "+l"(d) : "l"(a), "l"(b));
}
__device__ __forceinline__ unsigned long long pack2(float x, float y) {
    unsigned long long r;
    asm("mov.b64 %0, {%1, %2};" : "=l"(r) : "f"(x), "f"(y));
    return r;
}
__device__ __forceinline__ float2 unpack2(unsigned long long v) {
    float2 r;
    asm("mov.b64 {%0, %1}, %2;" : "=f"(r.x), "=f"(r.y) : "l"(v));
    return r;
}

// ---------------- SGEMM: C[M,N] = A[M,K] @ B[K,N] (+bias), fp32 ------------
// 128x128 tile, 256 threads, 8x8 microtile via packed FFMA2, BK=16,
// double-buffered smem. Requires M%128==0, N%128==0, K%16==0.
#define ASTRIDE 132
__global__ void __launch_bounds__(256, 2)
sgemm128(const float* __restrict__ A, const float* __restrict__ Bm,
         const float* __restrict__ bias, float* __restrict__ Cm,
         int M, int N, int K) {
    __shared__ float As[2][16][ASTRIDE];
    __shared__ float Bs[2][16][ASTRIDE];
    const int tid = threadIdx.x;
    const int row0 = blockIdx.y * 128;
    const int col0 = blockIdx.x * 128;
    const int ar = tid >> 2, ac = (tid & 3) << 2;
    const int br = tid >> 5, bc = (tid & 31) << 2;
    const int tx = tid & 15, ty = tid >> 4;
    const float* Ap = A + (size_t)(row0 + ar) * K;
    const float* Ap2 = Ap + (size_t)64 * K;

    float4 a0, a1, b0, b1;
    a0 = *(const float4*)(Ap + ac);
    a1 = *(const float4*)(Ap2 + ac);
    b0 = *(const float4*)(Bm + (size_t)br * N + col0 + bc);
    b1 = *(const float4*)(Bm + (size_t)(br + 8) * N + col0 + bc);
    As[0][ac + 0][ar] = a0.x; As[0][ac + 1][ar] = a0.y;
    As[0][ac + 2][ar] = a0.z; As[0][ac + 3][ar] = a0.w;
    As[0][ac + 0][ar + 64] = a1.x; As[0][ac + 1][ar + 64] = a1.y;
    As[0][ac + 2][ar + 64] = a1.z; As[0][ac + 3][ar + 64] = a1.w;
    *(float4*)&Bs[0][br][bc] = b0;
    *(float4*)&Bs[0][br + 8][bc] = b1;
    __syncthreads();

    unsigned long long acc2[8][4];
#pragma unroll
    for (int i = 0; i < 8; i++)
#pragma unroll
        for (int j = 0; j < 4; j++) acc2[i][j] = 0ull;

    const int ntiles = K >> 4;
    int buf = 0;
    for (int kt = 0; kt < ntiles; kt++) {
        if (kt + 1 < ntiles) {
            const int k0 = (kt + 1) << 4;
            a0 = *(const float4*)(Ap + k0 + ac);
            a1 = *(const float4*)(Ap2 + k0 + ac);
            b0 = *(const float4*)(Bm + (size_t)(k0 + br) * N + col0 + bc);
            b1 = *(const float4*)(Bm + (size_t)(k0 + br + 8) * N + col0 + bc);
        }
#pragma unroll
        for (int kk = 0; kk < 16; kk++) {
            float a[8], b[8];
            *(float4*)(a)     = *(const float4*)&As[buf][kk][ty * 8];
            *(float4*)(a + 4) = *(const float4*)&As[buf][kk][ty * 8 + 4];
            *(float4*)(b)     = *(const float4*)&Bs[buf][kk][tx * 8];
            *(float4*)(b + 4) = *(const float4*)&Bs[buf][kk][tx * 8 + 4];
            unsigned long long bp[4];
            bp[0] = pack2(b[0], b[1]); bp[1] = pack2(b[2], b[3]);
            bp[2] = pack2(b[4], b[5]); bp[3] = pack2(b[6], b[7]);
#pragma unroll
            for (int i = 0; i < 8; i++) {
                const unsigned long long ad = pack2(a[i], a[i]);
                ffma2(acc2[i][0], ad, bp[0]);
                ffma2(acc2[i][1], ad, bp[1]);
                ffma2(acc2[i][2], ad, bp[2]);
                ffma2(acc2[i][3], ad, bp[3]);
            }
        }
        if (kt + 1 < ntiles) {
            __syncthreads();
            const int nb = buf ^ 1;
            As[nb][ac + 0][ar] = a0.x; As[nb][ac + 1][ar] = a0.y;
            As[nb][ac + 2][ar] = a0.z; As[nb][ac + 3][ar] = a0.w;
            As[nb][ac + 0][ar + 64] = a1.x; As[nb][ac + 1][ar + 64] = a1.y;
            As[nb][ac + 2][ar + 64] = a1.z; As[nb][ac + 3][ar + 64] = a1.w;
            *(float4*)&Bs[nb][br][bc] = b0;
            *(float4*)&Bs[nb][br + 8][bc] = b1;
            __syncthreads();
            buf = nb;
        }
    }
    float bv[8];
    if (bias) {
        *(float4*)(bv)     = *(const float4*)&bias[col0 + tx * 8];
        *(float4*)(bv + 4) = *(const float4*)&bias[col0 + tx * 8 + 4];
    } else {
#pragma unroll
        for (int j = 0; j < 8; j++) bv[j] = 0.f;
    }
#pragma unroll
    for (int i = 0; i < 8; i++) {
        const int r = row0 + ty * 8 + i;
        const float2 c0 = unpack2(acc2[i][0]);
        const float2 c1 = unpack2(acc2[i][1]);
        const float2 c2 = unpack2(acc2[i][2]);
        const float2 c3 = unpack2(acc2[i][3]);
        float4 o0, o1;
        o0.x = c0.x + bv[0]; o0.y = c0.y + bv[1];
        o0.z = c1.x + bv[2]; o0.w = c1.y + bv[3];
        o1.x = c2.x + bv[4]; o1.y = c2.y + bv[5];
        o1.z = c3.x + bv[6]; o1.w = c3.y + bv[7];
        *(float4*)&Cm[(size_t)r * N + col0 + tx * 8] = o0;
        *(float4*)&Cm[(size_t)r * N + col0 + tx * 8 + 4] = o1;
    }
}

// ---------------- single-kernel CSR build (1 CTA per graph) -----------------
// Edge list is grouped by graph: edges [g*EPG, (g+1)*EPG) all have src/dst in
// [g*NPG, (g+1)*NPG). Histogram + scan + scatter entirely in smem.
__global__ void __launch_bounds__(256)
csr_build(const int* __restrict__ ei) {
    __shared__ int cnt[NPG];
    __shared__ int sh[256];
    const int g = blockIdx.x, tid = threadIdx.x;
    const int ebase = g * EPG, nbase = g * NPG;
    cnt[tid] = 0; cnt[tid + 256] = 0;
    __syncthreads();
#pragma unroll
    for (int i = tid; i < EPG; i += 256)
        atomicAdd(&cnt[ei[EE + ebase + i] - nbase], 1);
    __syncthreads();
    // block exclusive scan over 512 bins (thread t owns bins 2t, 2t+1)
    const int c0 = cnt[2 * tid], c1 = cnt[2 * tid + 1];
    const int tot = c0 + c1;
    sh[tid] = tot;
    __syncthreads();
    for (int s = 1; s < 256; s <<= 1) {
        const int v = (tid >= s) ? sh[tid - s] : 0;
        __syncthreads();
        sh[tid] += v;
        __syncthreads();
    }
    const int base = sh[tid] - tot;
    g_off[nbase + 2 * tid]     = ebase + base;
    g_off[nbase + 2 * tid + 1] = ebase + base + c0;
    cnt[2 * tid] = base;
    cnt[2 * tid + 1] = base + c0;
    if (g == BB - 1 && tid == 0) g_off[NN] = EE;
    __syncthreads();
#pragma unroll
    for (int i = tid; i < EPG; i += 256) {
        const int d = ei[EE + ebase + i] - nbase;
        const int p = atomicAdd(&cnt[d], 1);
        g_csrc[ebase + p] = ei[ebase + i];
    }
}

// ---------------- attention logits: es/ed per (node, head) -----------------
__global__ void esed_kernel(const float* __restrict__ hlin,
                            const float* __restrict__ a_src,
                            const float* __restrict__ a_dst,
                            float* __restrict__ es, float* __restrict__ ed) {
    const int w = (blockIdx.x * blockDim.x + threadIdx.x) >> 5;  // (n*H+h)
    const int lane = threadIdx.x & 31;
    if (w >= NN * HH) return;
    const int n = w >> 2, h = w & 3;
    const float* hp = hlin + (size_t)n * CC + h * FH;
    const float v0 = hp[lane], v1 = hp[lane + 32];
    float s = v0 * a_src[h * FH + lane] + v1 * a_src[h * FH + lane + 32];
    float d = v0 * a_dst[h * FH + lane] + v1 * a_dst[h * FH + lane + 32];
#pragma unroll
    for (int o = 16; o; o >>= 1) {
        s += __shfl_xor_sync(0xffffffffu, s, o);
        d += __shfl_xor_sync(0xffffffffu, d, o);
    }
    if (lane == 0) { es[w] = s; ed[w] = d; }
}

// ---------------- fused softmax + aggregate + bias + ELU --------------------
// One warp per dst node. Edge weights computed in registers (one edge per
// lane per 32-chunk), broadcast via shfl; h rows read as 2x LDG.128/lane.
// Softmax without max-subtraction (ratio-invariant; logits are O(10)).
__global__ void __launch_bounds__(256)
gat_fused(const int* __restrict__ off, const int* __restrict__ csrc,
          const float* __restrict__ es, const float* __restrict__ ed,
          const float* __restrict__ hlin, const float* __restrict__ bias,
          float* __restrict__ out) {
    const int n = (blockIdx.x * blockDim.x + threadIdx.x) >> 5;
    const int lane = threadIdx.x & 31;
    if (n >= NN) return;

    const float4 edv = ((const float4*)ed)[n];
    const float4 esv = ((const float4*)es)[n];
    // self-loop unnormalized weights per head
    const float xs0 = __expf(leaky(esv.x + edv.x));
    const float xs1 = __expf(leaky(esv.y + edv.y));
    const float xs2 = __expf(leaky(esv.z + edv.z));
    const float xs3 = __expf(leaky(esv.w + edv.w));

    const int hi = lane >> 4;  // 0: cols [0,64) of each 128-half; 1: [64,128)
    const float4* hn = (const float4*)(hlin + (size_t)n * CC);
    float4 acc0 = hn[lane];        // cols 4*lane   .. +3   (heads 0/1)
    float4 acc1 = hn[32 + lane];   // cols 128+4*lane .. +3 (heads 2/3)
    const float sa0 = hi ? xs1 : xs0;
    const float sa1 = hi ? xs3 : xs2;
    acc0.x *= sa0; acc0.y *= sa0; acc0.z *= sa0; acc0.w *= sa0;
    acc1.x *= sa1; acc1.y *= sa1; acc1.z *= sa1; acc1.w *= sa1;

    float ts0 = 0.f, ts1 = 0.f, ts2 = 0.f, ts3 = 0.f;
    const int o0 = off[n], o1 = off[n + 1];
    for (int base = o0; base < o1; base += 32) {
        const int cnt = min(32, o1 - base);
        int s = 0;
        float t0 = 0.f, t1 = 0.f, t2 = 0.f, t3 = 0.f;
        if (lane < cnt) {
            s = csrc[base + lane];
            const float4 ess = ((const float4*)es)[s];
            t0 = __expf(leaky(ess.x + edv.x));
            t1 = __expf(leaky(ess.y + edv.y));
            t2 = __expf(leaky(ess.z + edv.z));
            t3 = __expf(leaky(ess.w + edv.w));
        }
        ts0 += t0; ts1 += t1; ts2 += t2; ts3 += t3;

        // prefetch edge 0's row
        int se = __shfl_sync(0xffffffffu, s, 0);
        const float4* hs = (const float4*)(hlin + (size_t)se * CC);
        float4 v0n = hs[lane], v1n = hs[32 + lane];
        for (int e = 0; e < cnt; e++) {
            const float4 v0 = v0n, v1 = v1n;
            const float w0 = __shfl_sync(0xffffffffu, t0, e);
            const float w1 = __shfl_sync(0xffffffffu, t1, e);
            const float w2 = __shfl_sync(0xffffffffu, t2, e);
            const float w3 = __shfl_sync(0xffffffffu, t3, e);
            if (e + 1 < cnt) {
                se = __shfl_sync(0xffffffffu, s, e + 1);
                const float4* hsn = (const float4*)(hlin + (size_t)se * CC);
                v0n = hsn[lane]; v1n = hsn[32 + lane];
            }
            const float aw0 = hi ? w1 : w0;
            const float aw1 = hi ? w3 : w2;
            acc0.x += aw0 * v0.x; acc0.y += aw0 * v0.y;
            acc0.z += aw0 * v0.z; acc0.w += aw0 * v0.w;
            acc1.x += aw1 * v1.x; acc1.y += aw1 * v1.y;
            acc1.z += aw1 * v1.z; acc1.w += aw1 * v1.w;
        }
    }
#pragma unroll
    for (int o = 16; o; o >>= 1) {
        ts0 += __shfl_xor_sync(0xffffffffu, ts0, o);
        ts1 += __shfl_xor_sync(0xffffffffu, ts1, o);
        ts2 += __shfl_xor_sync(0xffffffffu, ts2, o);
        ts3 += __shfl_xor_sync(0xffffffffu, ts3, o);
    }
    const float di0 = 1.f / (xs0 + ts0 + 1e-16f);
    const float di1 = 1.f / (xs1 + ts1 + 1e-16f);
    const float di2 = 1.f / (xs2 + ts2 + 1e-16f);
    const float di3 = 1.f / (xs3 + ts3 + 1e-16f);
    const float d0 = hi ? di1 : di0;
    const float d1 = hi ? di3 : di2;

    const float4 bv0 = ((const float4*)bias)[lane];
    const float4 bv1 = ((const float4*)bias)[32 + lane];
    float4 o0v, o1v;
    o0v.x = acc0.x * d0 + bv0.x; o0v.y = acc0.y * d0 + bv0.y;
    o0v.z = acc0.z * d0 + bv0.z; o0v.w = acc0.w * d0 + bv0.w;
    o1v.x = acc1.x * d1 + bv1.x; o1v.y = acc1.y * d1 + bv1.y;
    o1v.z = acc1.z * d1 + bv1.z; o1v.w = acc1.w * d1 + bv1.w;
    o0v.x = o0v.x > 0.f ? o0v.x : (__expf(o0v.x) - 1.f);
    o0v.y = o0v.y > 0.f ? o0v.y : (__expf(o0v.y) - 1.f);
    o0v.z = o0v.z > 0.f ? o0v.z : (__expf(o0v.z) - 1.f);
    o0v.w = o0v.w > 0.f ? o0v.w : (__expf(o0v.w) - 1.f);
    o1v.x = o1v.x > 0.f ? o1v.x : (__expf(o1v.x) - 1.f);
    o1v.y = o1v.y > 0.f ? o1v.y : (__expf(o1v.y) - 1.f);
    o1v.z = o1v.z > 0.f ? o1v.z : (__expf(o1v.z) - 1.f);
    o1v.w = o1v.w > 0.f ? o1v.w : (__expf(o1v.w) - 1.f);
    ((float4*)out)[(size_t)n * 64 + lane]      = o0v;
    ((float4*)out)[(size_t)n * 64 + 32 + lane] = o1v;
}

// ---------------- pooling ---------------------------------------------------
__global__ void score_kernel(const float* __restrict__ X, const float* __restrict__ sw,
                             const float* __restrict__ sb, float* __restrict__ scores,
                             int rows) {
    const int w = (blockIdx.x * blockDim.x + threadIdx.x) >> 5;
    const int lane = threadIdx.x & 31;
    if (w >= rows) return;
    float s = 0.f;
#pragma unroll
    for (int c = lane; c < CC; c += 32) s += X[(size_t)w * CC + c] * sw[c];
#pragma unroll
    for (int o = 16; o; o >>= 1) s += __shfl_xor_sync(0xffffffffu, s, o);
    if (lane == 0) scores[w] = 1.f / (1.f + __expf(-(s + sb[0])));
}

template <int NPB, int KSEL>
__global__ void topk_kernel(const float* __restrict__ scores, int* __restrict__ idx_out) {
    __shared__ float sv[NPB];
    __shared__ int si[NPB];
    const int b = blockIdx.x, t = threadIdx.x;
    sv[t] = scores[b * NPB + t];
    si[t] = t;
    __syncthreads();
    for (int k = 2; k <= NPB; k <<= 1) {
        for (int j = k >> 1; j > 0; j >>= 1) {
            const int ixj = t ^ j;
            if (ixj > t) {
                const bool desc = ((t & k) == 0);
                const float a = sv[t], c = sv[ixj];
                if ((a < c) == desc) {
                    sv[t] = c; sv[ixj] = a;
                    const int tmp = si[t]; si[t] = si[ixj]; si[ixj] = tmp;
                }
            }
            __syncthreads();
        }
    }
    if (t < KSEL) idx_out[b * KSEL + t] = b * NPB + si[t];
}

__global__ void gather_kernel(const float* __restrict__ X, const int* __restrict__ idx,
                              float* __restrict__ out, int rows) {
    const int g = blockIdx.x * blockDim.x + threadIdx.x;
    if (g >= rows * 64) return;
    const int r = g >> 6, c4 = (g & 63) * 4;
    const float4 v = *reinterpret_cast<const float4*>(&X[(size_t)idx[r] * CC + c4]);
    *reinterpret_cast<float4*>(&out[(size_t)r * CC + c4]) = v;
}

// ---------------- readout ---------------------------------------------------
__global__ void mean_kernel(const float* __restrict__ X, float* __restrict__ g) {
    const int i = blockIdx.x * blockDim.x + threadIdx.x;
    if (i >= BB * CC) return;
    const int b = i >> 8, c = i & 255;
    float s = 0.f;
    for (int r = 0; r < K2; r++) s += X[(size_t)(b * K2 + r) * CC + c];
    g[i] = s * (1.f / K2);
}

__global__ void fc1_kernel(const float* __restrict__ g, const float* __restrict__ w,
                           const float* __restrict__ bias, float* __restrict__ out) {
    const int i = blockIdx.x * blockDim.x + threadIdx.x;
    if (i >= BB * 64) return;
    const int b = i >> 6, o = i & 63;
    float s = bias[o];
    for (int k = 0; k < CC; k++) s += g[b * CC + k] * w[k * 64 + o];
    out[i] = s > 0.f ? s : 0.f;
}

__global__ void fc2_lsm_kernel(const float* __restrict__ f, const float* __restrict__ w,
                               const float* __restrict__ bias, float* __restrict__ out) {
    const int b = threadIdx.x;
    if (b >= BB) return;
    float l0 = bias[0], l1 = bias[1];
    for (int k = 0; k < 64; k++) {
        const float v = f[b * 64 + k];
        l0 += v * w[k * 2 + 0];
        l1 += v * w[k * 2 + 1];
    }
    const float mm = fmaxf(l0, l1);
    const float lse = mm + logf(__expf(l0 - mm) + __expf(l1 - mm));
    out[b * 2 + 0] = l0 - lse;
    out[b * 2 + 1] = l1 - lse;
}

// ---------------- host orchestration ----------------------------------------
static float* sym(const void* s) {
    void* p = nullptr;
    cudaGetSymbolAddress(&p, (const void*)s);
    return (float*)p;
}

extern "C" void kernel_launch(void* const* d_in, const int* in_sizes, int n_in,
                              void* d_out, int out_size) {
    const float* x      = (const float*)d_in[0];
    const int*   ei     = (const int*)  d_in[1];
    const float* W1     = (const float*)d_in[3];
    const float* asrc1  = (const float*)d_in[4];
    const float* adst1  = (const float*)d_in[5];
    const float* b1     = (const float*)d_in[6];
    const float* W2     = (const float*)d_in[7];
    const float* asrc2  = (const float*)d_in[8];
    const float* adst2  = (const float*)d_in[9];
    const float* b2     = (const float*)d_in[10];
    const float* p1_sw  = (const float*)d_in[11];
    const float* p1_sb  = (const float*)d_in[12];
    const float* p1_tw  = (const float*)d_in[13];
    const float* p1_tb  = (const float*)d_in[14];
    const float* p2_sw  = (const float*)d_in[15];
    const float* p2_sb  = (const float*)d_in[16];
    const float* p2_tw  = (const float*)d_in[17];
    const float* p2_tb  = (const float*)d_in[18];
    const float* c1w    = (const float*)d_in[19];
    const float* c1b    = (const float*)d_in[20];
    const float* c2w    = (const float*)d_in[21];
    const float* c2b    = (const float*)d_in[22];
    float* out = (float*)d_out;

    float*    hlin  = sym(g_hlin);
    float*    hout  = sym(g_hout);
    float*    es    = sym(g_es);
    float*    ed    = sym(g_ed);
    int*      off   = (int*)sym(g_off);
    int*      csrc  = (int*)sym(g_csrc);
    float*    selb  = sym(g_sel);
    float*    pool1 = sym(g_pool1);
    float*    pool2 = sym(g_pool2);
    int*      idx   = (int*)sym(g_idx);
    float*    sc    = sym(g_scores);
    float*    gmean = sym(g_gmean);
    float*    fc1   = sym(g_fc1);

    dim3 t256(256);

    // ---- CSR build (one kernel; graph shared by both layers) ----
    csr_build<<<BB, t256>>>(ei);

    // ---- GAT layer 1 ----
    sgemm128<<<dim3(CC / 128, NN / 128), t256>>>(x, W1, nullptr, hlin, NN, CC, FIN);
    esed_kernel<<<(NN * HH) / 8, t256>>>(hlin, asrc1, adst1, es, ed);
    gat_fused<<<(NN * 32) / 256, t256>>>(off, csrc, es, ed, hlin, b1, hout);

    // ---- GAT layer 2 ----
    sgemm128<<<dim3(CC / 128, NN / 128), t256>>>(hout, W2, nullptr, hlin, NN, CC, CC);
    esed_kernel<<<(NN * HH) / 8, t256>>>(hlin, asrc2, adst2, es, ed);
    gat_fused<<<(NN * 32) / 256, t256>>>(off, csrc, es, ed, hlin, b2, hout);

    // ---- Pool 1 (top-256 of 512 per graph) ----
    score_kernel<<<(NN * 32) / 256, t256>>>(hout, p1_sw, p1_sb, sc, NN);
    topk_kernel<NPG, K1><<<BB, NPG>>>(sc, idx);
    gather_kernel<<<(BB * K1 * 64) / 256, t256>>>(hout, idx, selb, BB * K1);
    sgemm128<<<dim3(CC / 128, (BB * K1) / 128), t256>>>(selb, p1_tw, p1_tb, pool1, BB * K1, CC, CC);

    // ---- Pool 2 (top-128 of 256 per graph) ----
    score_kernel<<<(BB * K1 * 32) / 256, t256>>>(pool1, p2_sw, p2_sb, sc, BB * K1);
    topk_kernel<K1, K2><<<BB, K1>>>(sc, idx);
    gather_kernel<<<(BB * K2 * 64) / 256, t256>>>(pool1, idx, selb, BB * K2);
    sgemm128<<<dim3(CC / 128, (BB * K2) / 128), t256>>>(selb, p2_tw, p2_tb, pool2, BB * K2, CC, CC);

    // ---- readout ----
    mean_kernel<<<(BB * CC) / 256, t256>>>(pool2, gmean);
    fc1_kernel<<<(BB * 64) / 256, t256>>>(gmean, c1w, c1b, fc1);
    fc2_lsm_kernel<<<1, 64>>>(fc1, c2w, c2b, out);
}